// round 1
// baseline (speedup 1.0000x reference)
#include <cuda_runtime.h>

// y = (W1*x > W0*x) ? +1 : -1, elementwise over 37.75M floats.
// Pure HBM-streaming: 151MB in + 151MB out.

__global__ void metaconv_sign_kernel(const float4* __restrict__ x,
                                     const float* __restrict__ W,
                                     float4* __restrict__ out,
                                     int n4) {
    const float w0 = W[0];
    const float w1 = W[1];
    int i = blockIdx.x * blockDim.x + threadIdx.x;
    const int stride = gridDim.x * blockDim.x;
    #pragma unroll 4
    for (; i < n4; i += stride) {
        float4 v = x[i];
        float4 r;
        r.x = (w1 * v.x > w0 * v.x) ? 1.0f : -1.0f;
        r.y = (w1 * v.y > w0 * v.y) ? 1.0f : -1.0f;
        r.z = (w1 * v.z > w0 * v.z) ? 1.0f : -1.0f;
        r.w = (w1 * v.w > w0 * v.w) ? 1.0f : -1.0f;
        out[i] = r;
    }
}

// Scalar tail kernel in case N % 4 != 0 (not needed for this shape, but safe).
__global__ void metaconv_sign_tail(const float* __restrict__ x,
                                   const float* __restrict__ W,
                                   float* __restrict__ out,
                                   int start, int n) {
    const float w0 = W[0];
    const float w1 = W[1];
    int i = start + blockIdx.x * blockDim.x + threadIdx.x;
    if (i < n) {
        float v = x[i];
        out[i] = (w1 * v > w0 * v) ? 1.0f : -1.0f;
    }
}

extern "C" void kernel_launch(void* const* d_in, const int* in_sizes, int n_in,
                              void* d_out, int out_size) {
    const float* x = (const float*)d_in[0];
    const float* W = (const float*)d_in[1];
    float* out = (float*)d_out;

    const int n = in_sizes[0];
    const int n4 = n >> 2;

    if (n4 > 0) {
        const int threads = 256;
        // ~4 float4s per thread: enough MLP to saturate HBM, small launch overhead.
        int blocks = (n4 + threads * 4 - 1) / (threads * 4);
        if (blocks < 1) blocks = 1;
        metaconv_sign_kernel<<<blocks, threads>>>(
            (const float4*)x, W, (float4*)out, n4);
    }
    const int rem = n - (n4 << 2);
    if (rem > 0) {
        metaconv_sign_tail<<<1, 32>>>(x, W, out, n4 << 2, n);
    }
}

// round 2
// speedup vs baseline: 1.0020x; 1.0020x over previous
#include <cuda_runtime.h>

// y = (W1*x > W0*x) ? +1 : -1, elementwise over 37.75M floats.
// Pure HBM streaming: 151MB read + 151MB write. Memory-roofline bound.
// Each thread: 4 independent float4 loads front-batched (MLP=4), streaming
// cache hints (.cs) since data has zero reuse.

__global__ void __launch_bounds__(256)
metaconv_sign4_kernel(const float4* __restrict__ x,
                      const float* __restrict__ W,
                      float4* __restrict__ out,
                      int n4) {
    const float w0 = W[0];
    const float w1 = W[1];

    const int tile = blockIdx.x * (blockDim.x * 4) + threadIdx.x;
    const int i0 = tile;
    const int i1 = tile + 256;
    const int i2 = tile + 512;
    const int i3 = tile + 768;

    if (i3 < n4) {
        // Fast path: all 4 in-bounds. Front-batch the 4 loads.
        float4 v0 = __ldcs(&x[i0]);
        float4 v1 = __ldcs(&x[i1]);
        float4 v2 = __ldcs(&x[i2]);
        float4 v3 = __ldcs(&x[i3]);

        float4 r0, r1, r2, r3;
        r0.x = (w1 * v0.x > w0 * v0.x) ? 1.0f : -1.0f;
        r0.y = (w1 * v0.y > w0 * v0.y) ? 1.0f : -1.0f;
        r0.z = (w1 * v0.z > w0 * v0.z) ? 1.0f : -1.0f;
        r0.w = (w1 * v0.w > w0 * v0.w) ? 1.0f : -1.0f;
        r1.x = (w1 * v1.x > w0 * v1.x) ? 1.0f : -1.0f;
        r1.y = (w1 * v1.y > w0 * v1.y) ? 1.0f : -1.0f;
        r1.z = (w1 * v1.z > w0 * v1.z) ? 1.0f : -1.0f;
        r1.w = (w1 * v1.w > w0 * v1.w) ? 1.0f : -1.0f;
        r2.x = (w1 * v2.x > w0 * v2.x) ? 1.0f : -1.0f;
        r2.y = (w1 * v2.y > w0 * v2.y) ? 1.0f : -1.0f;
        r2.z = (w1 * v2.z > w0 * v2.z) ? 1.0f : -1.0f;
        r2.w = (w1 * v2.w > w0 * v2.w) ? 1.0f : -1.0f;
        r3.x = (w1 * v3.x > w0 * v3.x) ? 1.0f : -1.0f;
        r3.y = (w1 * v3.y > w0 * v3.y) ? 1.0f : -1.0f;
        r3.z = (w1 * v3.z > w0 * v3.z) ? 1.0f : -1.0f;
        r3.w = (w1 * v3.w > w0 * v3.w) ? 1.0f : -1.0f;

        __stcs(&out[i0], r0);
        __stcs(&out[i1], r1);
        __stcs(&out[i2], r2);
        __stcs(&out[i3], r3);
    } else {
        // Edge tile: per-element guard.
        #pragma unroll
        for (int k = 0; k < 4; k++) {
            int i = tile + k * 256;
            if (i < n4) {
                float4 v = __ldcs(&x[i]);
                float4 r;
                r.x = (w1 * v.x > w0 * v.x) ? 1.0f : -1.0f;
                r.y = (w1 * v.y > w0 * v.y) ? 1.0f : -1.0f;
                r.z = (w1 * v.z > w0 * v.z) ? 1.0f : -1.0f;
                r.w = (w1 * v.w > w0 * v.w) ? 1.0f : -1.0f;
                __stcs(&out[i], r);
            }
        }
    }
}

// Scalar tail kernel in case N % 4 != 0 (not needed for this shape, but safe).
__global__ void metaconv_sign_tail(const float* __restrict__ x,
                                   const float* __restrict__ W,
                                   float* __restrict__ out,
                                   int start, int n) {
    const float w0 = W[0];
    const float w1 = W[1];
    int i = start + blockIdx.x * blockDim.x + threadIdx.x;
    if (i < n) {
        float v = x[i];
        out[i] = (w1 * v > w0 * v) ? 1.0f : -1.0f;
    }
}

extern "C" void kernel_launch(void* const* d_in, const int* in_sizes, int n_in,
                              void* d_out, int out_size) {
    const float* x = (const float*)d_in[0];
    const float* W = (const float*)d_in[1];
    float* out = (float*)d_out;

    const int n = in_sizes[0];
    const int n4 = n >> 2;

    if (n4 > 0) {
        const int threads = 256;
        const int per_block = threads * 4;  // float4s per block
        int blocks = (n4 + per_block - 1) / per_block;
        metaconv_sign4_kernel<<<blocks, threads>>>(
            (const float4*)x, W, (float4*)out, n4);
    }
    const int rem = n - (n4 << 2);
    if (rem > 0) {
        metaconv_sign_tail<<<1, 32>>>(x, W, out, n4 << 2, n);
    }
}